// round 9
// baseline (speedup 1.0000x reference)
#include <cuda_runtime.h>
#include <cuda_bf16.h>
#include <math.h>
#include <stdint.h>

// Problem constants
#define B_      4096
#define SQ_     81
#define D_      256
#define P_      3849
#define NDROP_  7
#define MROWS   (B_ * SQ_)          // 331776
#define SCALE_  0.0625f             // 1/sqrt(256)

// ---------------- device scratch (static, no allocs) ----------------
__device__ __nv_bfloat16 g_peH[84934656], g_peL[84934656];   // pe split (MROWS*256)
__device__ __nv_bfloat16 g_GH [84934656], g_GL [84934656];   // G split
__device__ float g_A [D_ * D_];     // s * Wq @ Wk^T
__device__ float g_Dq2[NDROP_ * D_];// s * Dq @ Wk^T
__device__ __nv_bfloat16 g_Dq2H[NDROP_ * D_], g_Dq2L[NDROP_ * D_];
__device__ float g_wkp[D_];         // Wk @ Wp
__device__ float g_u[D_];           // s * Wq @ bk
__device__ float g_v[D_];           // s * Wk @ bq
__device__ float g_koff[MROWS];
__device__ float g_pu[MROWS];
__device__ float g_pv[MROWS];
__device__ float g_dn[NDROP_];      // s * Dq @ bk
__device__ float g_consts[2];       // [0] = s*(bq.bk), [1] = bk.Wp + bp
__device__ int   g_src2[P_];        // packed col | row<<7 | promo<<14

// bf16 split weights (transposed to [n][k]):
__device__ __nv_bfloat16 g_W1h[65536], g_W1l[65536];   // We^T  hi/lo
__device__ __nv_bfloat16 g_W2h[65536], g_W2l[65536];   // A^T   hi/lo

// ================= portable PTX helpers (sm_80+ ISA only) =================
__device__ __forceinline__ uint32_t smem_u32(const void* p) {
    uint32_t a;
    asm("{ .reg .u64 t; cvta.to.shared.u64 t, %1; cvt.u32.u64 %0, t; }" : "=r"(a) : "l"(p));
    return a;
}

#define LDSM4(r, addr) \
    asm volatile("ldmatrix.sync.aligned.m8n8.x4.shared.b16 {%0,%1,%2,%3}, [%4];" \
        : "=r"((r)[0]), "=r"((r)[1]), "=r"((r)[2]), "=r"((r)[3]) : "r"(addr))

#define MMA_BF16(c, a, b) \
    asm volatile("mma.sync.aligned.m16n8k16.row.col.f32.bf16.bf16.f32 " \
        "{%0,%1,%2,%3}, {%4,%5,%6,%7}, {%8,%9}, {%0,%1,%2,%3};" \
        : "+f"((c)[0]), "+f"((c)[1]), "+f"((c)[2]), "+f"((c)[3]) \
        : "r"((a)[0]), "r"((a)[1]), "r"((a)[2]), "r"((a)[3]), \
          "r"((b)[0]), "r"((b)[1]))

#define CP_ASYNC16(saddr, gptr) \
    asm volatile("cp.async.cg.shared.global [%0], [%1], 16;" :: "r"(saddr), "l"(gptr))
#define CP_COMMIT()  asm volatile("cp.async.commit_group;" ::: "memory")
#define CP_WAIT0()   asm volatile("cp.async.wait_group 0;" ::: "memory")
#define CP_WAIT1()   asm volatile("cp.async.wait_group 1;" ::: "memory")

__device__ __forceinline__ float mishf(float v)
{
    float sp = fmaxf(v, 0.f) + log1pf(__expf(-fabsf(v)));
    return v * tanhf(sp);
}

__device__ __forceinline__ void split2(float v0, float v1,
                                       __nv_bfloat162& h, __nv_bfloat162& l)
{
    h = __floats2bfloat162_rn(v0, v1);
    float2 hf = __bfloat1622float2(h);
    l = __floats2bfloat162_rn(v0 - hf.x, v1 - hf.y);
}

// ---------------- prep: small weight products ----------------
__global__ __launch_bounds__(256)
void prep_weights(const float* __restrict__ Wq, const float* __restrict__ Wk,
                  const float* __restrict__ Wp, const float* __restrict__ bq,
                  const float* __restrict__ bk, const float* __restrict__ bp,
                  const float* __restrict__ Dq)
{
    int blk = blockIdx.x;
    int t = threadIdx.x;
    if (blk < 256) {
        __shared__ float wq[256];
        wq[t] = Wq[blk * 256 + t];
        __syncthreads();
        const float* wkrow = Wk + (size_t)t * 256;
        float acc = 0.f;
        #pragma unroll 8
        for (int i = 0; i < 256; i++) acc = fmaf(wq[i], wkrow[i], acc);
        g_A[blk * 256 + t] = SCALE_ * acc;
    } else if (blk == 256) {
        __shared__ float dq[NDROP_ * 256];
        for (int idx = t; idx < NDROP_ * 256; idx += 256) dq[idx] = Dq[idx];
        __syncthreads();
        const float* wkrow = Wk + (size_t)t * 256;
        float a[NDROP_];
        #pragma unroll
        for (int n = 0; n < NDROP_; n++) a[n] = 0.f;
        for (int i = 0; i < 256; i++) {
            float w = wkrow[i];
            #pragma unroll
            for (int n = 0; n < NDROP_; n++) a[n] = fmaf(dq[n * 256 + i], w, a[n]);
        }
        #pragma unroll
        for (int n = 0; n < NDROP_; n++) g_Dq2[n * 256 + t] = SCALE_ * a[n];
    } else {
        __shared__ float wp[256], bks[256], bqs[256];
        wp[t] = Wp[t]; bks[t] = bk[t]; bqs[t] = bq[t];
        __syncthreads();
        const float* wkrow = Wk + (size_t)t * 256;
        const float* wqrow = Wq + (size_t)t * 256;
        float a0 = 0.f, a1 = 0.f, a2 = 0.f;
        for (int i = 0; i < 256; i++) {
            a0 = fmaf(wkrow[i], wp[i],  a0);
            a1 = fmaf(wqrow[i], bks[i], a1);
            a2 = fmaf(wkrow[i], bqs[i], a2);
        }
        g_wkp[t] = a0;
        g_u[t]   = SCALE_ * a1;
        g_v[t]   = SCALE_ * a2;
        if (t < NDROP_) {
            float s = 0.f;
            for (int i = 0; i < 256; i++) s = fmaf(Dq[t * 256 + i], bks[i], s);
            g_dn[t] = SCALE_ * s;
        }
        if (t == 0) {
            float c = 0.f, kb = 0.f;
            for (int i = 0; i < 256; i++) { c = fmaf(bqs[i], bks[i], c); kb = fmaf(bks[i], wp[i], kb); }
            g_consts[0] = SCALE_ * c;
            g_consts[1] = kb + bp[0];
        }
    }
}

// ---------------- prep: bf16 hi/lo splits -------------
__global__ __launch_bounds__(256)
void prep_split(const float* __restrict__ We)
{
    int n = blockIdx.x, k = threadIdx.x;
    if (n < 256) {
        float v1 = We[(size_t)k * 256 + n];              // We^T[n][k]
        __nv_bfloat16 h1 = __float2bfloat16(v1);
        g_W1h[n * 256 + k] = h1;
        g_W1l[n * 256 + k] = __float2bfloat16(v1 - __bfloat162float(h1));
        float v2 = g_A[(size_t)k * 256 + n];             // A^T[n][k]
        __nv_bfloat16 h2 = __float2bfloat16(v2);
        g_W2h[n * 256 + k] = h2;
        g_W2l[n * 256 + k] = __float2bfloat16(v2 - __bfloat162float(h2));
    } else {
        #pragma unroll
        for (int d = 0; d < NDROP_; d++) {
            float v = g_Dq2[d * 256 + k];
            __nv_bfloat16 h = __float2bfloat16(v);
            g_Dq2H[d * 256 + k] = h;
            g_Dq2L[d * 256 + k] = __float2bfloat16(v - __bfloat162float(h));
        }
    }
}

// ---------------- prep: inverse scatter map ----------------
__global__ void prep_src(const void* __restrict__ vraw, const void* __restrict__ vpol)
{
    const int* r32 = (const int*)vraw;
    bool is64 = (r32[1] == 0 && r32[3] == 0 && r32[5] == 0);
    int j = blockIdx.x * blockDim.x + threadIdx.x;
    if (j >= P_) return;
    long long r, pol;
    if (is64) {
        r   = ((const long long*)vraw)[j];
        pol = ((const long long*)vpol)[j];
    } else {
        r   = ((const int*)vraw)[j];
        pol = ((const int*)vpol)[j];
    }
    int ri = (int)r;
    int row, col, promo = 0;
    if (ri < 6561)       { row = ri / 81;               col = ri % 81; }
    else if (ri < 13122) { int u2 = ri - 6561;  row = u2 / 81;      col = u2 % 81; promo = 1; }
    else                 { int u2 = ri - 13122; row = 81 + u2 / 81; col = u2 % 81; }
    g_src2[(int)pol] = col | (row << 7) | (promo << 14);
}

// ================== GEMM1: pe = mish(x @ We + be), split-bf16 mma ==========
// smem: WH 0..64K, WL 64K..128K (resident), X 128K.. (2 stages x (hi16K+lo16K))
#define GS_WH   0
#define GS_WL   65536
#define GS_X    131072
#define GS_TOTAL 196608

__global__ __launch_bounds__(256, 1)
void tc_gemm1(const float* __restrict__ xin, const float* __restrict__ be)
{
    extern __shared__ char smem[];
    __shared__ float biasS[128];
    const uint32_t sb = smem_u32(smem);
    const int tid  = threadIdx.x;
    const int wid  = tid >> 5;
    const int lane = tid & 31;
    const int wm   = wid & 3;
    const int wn   = wid >> 2;
    const int m0 = blockIdx.x * 128;
    const int n0 = blockIdx.y * 128;

    const float* __restrict__ Xg = xin;
    const __nv_bfloat16* __restrict__ Wh = g_W1h + (size_t)n0 * 256;
    const __nv_bfloat16* __restrict__ Wl = g_W1l + (size_t)n0 * 256;

    if (tid < 128) biasS[tid] = be[n0 + tid];

    // resident W tiles (hi+lo), swizzled 512B rows
    #pragma unroll
    for (int i = 0; i < 32; i++) {
        int p = tid + i * 256;
        int half = p >> 12;
        int q = p & 4095;
        int row = q >> 5;
        int unit = q & 31;
        int phys = (unit & 24) | ((unit ^ row) & 7);
        uint32_t saddr = sb + (uint32_t)half * 65536u + (uint32_t)row * 512u + (uint32_t)phys * 16u;
        const __nv_bfloat16* gp = (half ? Wl : Wh) + (size_t)row * 256 + unit * 8;
        CP_ASYNC16(saddr, gp);
    }
    CP_COMMIT();

    const float* Xblk = Xg + (size_t)m0 * 256;
    float4 v[8];
    #pragma unroll
    for (int i = 0; i < 8; i++) {
        int p = tid + i * 256;
        int row = p >> 4, k4 = p & 15;
        v[i] = *(const float4*)(Xblk + (size_t)row * 256 + k4 * 4);
    }
    #pragma unroll
    for (int i = 0; i < 8; i++) {
        int p = tid + i * 256;
        int row = p >> 4, k4 = p & 15;
        int unit = k4 >> 1, sub = k4 & 1;
        uint32_t off = (uint32_t)row * 128u + (uint32_t)(((unit ^ row) & 7)) * 16u + (uint32_t)sub * 8u;
        __nv_bfloat162 h0, h1, l0, l1;
        split2(v[i].x, v[i].y, h0, l0);
        split2(v[i].z, v[i].w, h1, l1);
        uint2 hv, lv;
        hv.x = *(uint32_t*)&h0; hv.y = *(uint32_t*)&h1;
        lv.x = *(uint32_t*)&l0; lv.y = *(uint32_t*)&l1;
        *(uint2*)(smem + GS_X + off) = hv;
        *(uint2*)(smem + GS_X + 16384 + off) = lv;
    }
    CP_WAIT0();
    __syncthreads();

    float acc[2][8][4];
    #pragma unroll
    for (int mi = 0; mi < 2; mi++)
        #pragma unroll
        for (int nj = 0; nj < 8; nj++)
            #pragma unroll
            for (int r = 0; r < 4; r++) acc[mi][nj][r] = 0.f;

    for (int kc = 0; kc < 4; kc++) {
        const int buf = kc & 1;
        const uint32_t xh = sb + GS_X + (uint32_t)buf * 32768u;
        const uint32_t xl = xh + 16384u;

        if (kc < 3) {
            #pragma unroll
            for (int i = 0; i < 8; i++) {
                int p = tid + i * 256;
                int row = p >> 4, k4 = p & 15;
                v[i] = *(const float4*)(Xblk + (size_t)row * 256 + (kc + 1) * 64 + k4 * 4);
            }
        }

        #pragma unroll
        for (int k16 = 0; k16 < 4; k16++) {
            uint32_t ah[2][4], al[2][4];
            #pragma unroll
            for (int mi = 0; mi < 2; mi++) {
                int row = wm * 32 + mi * 16 + (lane & 15);
                int u = 2 * k16 + (lane >> 4);
                uint32_t off = (uint32_t)row * 128u + (uint32_t)((u ^ row) & 7) * 16u;
                LDSM4(ah[mi], xh + off);
                LDSM4(al[mi], xl + off);
            }
            uint32_t bh[8][2], bl[8][2];
            const int kk = kc * 4 + k16;
            #pragma unroll
            for (int j = 0; j < 4; j++) {
                int row = wn * 64 + j * 16 + (lane & 7) + ((lane >> 1) & 8);
                int u = 2 * kk + ((lane >> 3) & 1);
                uint32_t off = (uint32_t)row * 512u + (uint32_t)((u & 24) | ((u ^ row) & 7)) * 16u;
                uint32_t t[4];
                LDSM4(t, sb + GS_WH + off);
                bh[2*j][0] = t[0]; bh[2*j][1] = t[1]; bh[2*j+1][0] = t[2]; bh[2*j+1][1] = t[3];
                LDSM4(t, sb + GS_WL + off);
                bl[2*j][0] = t[0]; bl[2*j][1] = t[1]; bl[2*j+1][0] = t[2]; bl[2*j+1][1] = t[3];
            }
            #pragma unroll
            for (int mi = 0; mi < 2; mi++)
                #pragma unroll
                for (int nj = 0; nj < 8; nj++) {
                    MMA_BF16(acc[mi][nj], ah[mi], bh[nj]);
                    MMA_BF16(acc[mi][nj], ah[mi], bl[nj]);
                    MMA_BF16(acc[mi][nj], al[mi], bh[nj]);
                }
        }

        if (kc < 3) {
            const uint32_t nbuf = (kc + 1) & 1;
            __syncthreads();
            #pragma unroll
            for (int i = 0; i < 8; i++) {
                int p = tid + i * 256;
                int row = p >> 4, k4 = p & 15;
                int unit = k4 >> 1, sub = k4 & 1;
                uint32_t off = (uint32_t)nbuf * 32768u + (uint32_t)row * 128u
                             + (uint32_t)(((unit ^ row) & 7)) * 16u + (uint32_t)sub * 8u;
                __nv_bfloat162 h0, h1, l0, l1;
                split2(v[i].x, v[i].y, h0, l0);
                split2(v[i].z, v[i].w, h1, l1);
                uint2 hv, lv;
                hv.x = *(uint32_t*)&h0; hv.y = *(uint32_t*)&h1;
                lv.x = *(uint32_t*)&l0; lv.y = *(uint32_t*)&l1;
                *(uint2*)(smem + GS_X + off) = hv;
                *(uint2*)(smem + GS_X + 16384 + off) = lv;
            }
            __syncthreads();
        }
    }

    // epilogue: mish + split-bf16 write of pe
    const int mrow0 = m0 + wm * 32;
    const int ncol0 = wn * 64;
    #pragma unroll
    for (int mi = 0; mi < 2; mi++) {
        #pragma unroll
        for (int half = 0; half < 2; half++) {
            int m = mrow0 + mi * 16 + half * 8 + (lane >> 2);
            #pragma unroll
            for (int nj = 0; nj < 8; nj++) {
                int cl = ncol0 + nj * 8 + 2 * (lane & 3);
                float v0 = mishf(acc[mi][nj][half * 2 + 0] + biasS[cl]);
                float v1 = mishf(acc[mi][nj][half * 2 + 1] + biasS[cl + 1]);
                __nv_bfloat162 h, l;
                split2(v0, v1, h, l);
                *(__nv_bfloat162*)(g_peH + (size_t)m * 256 + n0 + cl) = h;
                *(__nv_bfloat162*)(g_peL + (size_t)m * 256 + n0 + cl) = l;
            }
        }
    }
}

// ================== GEMM2: G = pe @ A^T, pure cp.async/bf16 loop ===========
__global__ __launch_bounds__(256, 1)
void tc_gemm2()
{
    extern __shared__ char smem[];
    const uint32_t sb = smem_u32(smem);
    const int tid  = threadIdx.x;
    const int wid  = tid >> 5;
    const int lane = tid & 31;
    const int wm   = wid & 3;
    const int wn   = wid >> 2;
    const int m0 = blockIdx.x * 128;
    const int n0 = blockIdx.y * 128;

    const __nv_bfloat16* __restrict__ Wh = g_W2h + (size_t)n0 * 256;
    const __nv_bfloat16* __restrict__ Wl = g_W2l + (size_t)n0 * 256;

    // group 0: resident W
    #pragma unroll
    for (int i = 0; i < 32; i++) {
        int p = tid + i * 256;
        int half = p >> 12;
        int q = p & 4095;
        int row = q >> 5;
        int unit = q & 31;
        int phys = (unit & 24) | ((unit ^ row) & 7);
        uint32_t saddr = sb + (uint32_t)half * 65536u + (uint32_t)row * 512u + (uint32_t)phys * 16u;
        const __nv_bfloat16* gp = (half ? Wl : Wh) + (size_t)row * 256 + unit * 8;
        CP_ASYNC16(saddr, gp);
    }
    CP_COMMIT();

    // X stages: [128 rows][64 k] bf16, 128B rows, hi+lo
    auto issue_stage = [&](int kc) {
        const uint32_t st = GS_X + (uint32_t)(kc & 1) * 32768u;
        #pragma unroll
        for (int half = 0; half < 2; half++) {
            const __nv_bfloat16* src = (half ? g_peL : g_peH);
            #pragma unroll
            for (int i = 0; i < 4; i++) {
                int p = tid + i * 256;          // 0..1023
                int row = p >> 3, unit = p & 7;
                uint32_t off = st + (uint32_t)half * 16384u + (uint32_t)row * 128u
                             + (uint32_t)((unit ^ row) & 7) * 16u;
                CP_ASYNC16(sb + off, src + (size_t)(m0 + row) * 256 + kc * 64 + unit * 8);
            }
        }
        CP_COMMIT();
    };
    issue_stage(0);
    issue_stage(1);

    float acc[2][8][4];
    #pragma unroll
    for (int mi = 0; mi < 2; mi++)
        #pragma unroll
        for (int nj = 0; nj < 8; nj++)
            #pragma unroll
            for (int r = 0; r < 4; r++) acc[mi][nj][r] = 0.f;

    for (int kc = 0; kc < 4; kc++) {
        if (kc < 3) { CP_WAIT1(); } else { CP_WAIT0(); }
        __syncthreads();
        const uint32_t xh = sb + GS_X + (uint32_t)(kc & 1) * 32768u;
        const uint32_t xl = xh + 16384u;

        #pragma unroll
        for (int k16 = 0; k16 < 4; k16++) {
            uint32_t ah[2][4], al[2][4];
            #pragma unroll
            for (int mi = 0; mi < 2; mi++) {
                int row = wm * 32 + mi * 16 + (lane & 15);
                int u = 2 * k16 + (lane >> 4);
                uint32_t off = (uint32_t)row * 128u + (uint32_t)((u ^ row) & 7) * 16u;
                LDSM4(ah[mi], xh + off);
                LDSM4(al[mi], xl + off);
            }
            uint32_t bh[8][2], bl[8][2];
            const int kk = kc * 4 + k16;
            #pragma unroll
            for (int j = 0; j < 4; j++) {
                int row = wn * 64 + j * 16 + (lane & 7) + ((lane >> 1) & 8);
                int u = 2 * kk + ((lane >> 3) & 1);
                uint32_t off = (uint32_t)row * 512u + (uint32_t)((u & 24) | ((u ^ row) & 7)) * 16u;
                uint32_t t[4];
                LDSM4(t, sb + GS_WH + off);
                bh[2*j][0] = t[0]; bh[2*j][1] = t[1]; bh[2*j+1][0] = t[2]; bh[2*j+1][1] = t[3];
                LDSM4(t, sb + GS_WL + off);
                bl[2*j][0] = t[0]; bl[2*j][1] = t[1]; bl[2*j+1][0] = t[2]; bl[2*j+1][1] = t[3];
            }
            #pragma unroll
            for (int mi = 0; mi < 2; mi++)
                #pragma unroll
                for (int nj = 0; nj < 8; nj++) {
                    MMA_BF16(acc[mi][nj], ah[mi], bh[nj]);
                    MMA_BF16(acc[mi][nj], ah[mi], bl[nj]);
                    MMA_BF16(acc[mi][nj], al[mi], bh[nj]);
                }
        }
        __syncthreads();
        if (kc < 2) issue_stage(kc + 2);
    }

    // epilogue: split-bf16 write of G
    const int mrow0 = m0 + wm * 32;
    const int ncol0 = wn * 64;
    #pragma unroll
    for (int mi = 0; mi < 2; mi++) {
        #pragma unroll
        for (int half = 0; half < 2; half++) {
            int m = mrow0 + mi * 16 + half * 8 + (lane >> 2);
            #pragma unroll
            for (int nj = 0; nj < 8; nj++) {
                int cl = ncol0 + nj * 8 + 2 * (lane & 3);
                __nv_bfloat162 h, l;
                split2(acc[mi][nj][half * 2 + 0], acc[mi][nj][half * 2 + 1], h, l);
                *(__nv_bfloat162*)(g_GH + (size_t)m * 256 + n0 + cl) = h;
                *(__nv_bfloat162*)(g_GL + (size_t)m * 256 + n0 + cl) = l;
            }
        }
    }
}

// ---------------- per-row dots: koff / pu / pv (split-pe input) ------------
__global__ __launch_bounds__(256)
void koff_kernel()
{
    __shared__ float w0[256], w1[256], w2[256];
    int t = threadIdx.x;
    w0[t] = g_wkp[t]; w1[t] = g_u[t]; w2[t] = g_v[t];
    __syncthreads();
    int warp = t >> 5, lane = t & 31;
    int row = blockIdx.x * 8 + warp;
    const uint4* prH = (const uint4*)(g_peH + (size_t)row * 256);
    const uint4* prL = (const uint4*)(g_peL + (size_t)row * 256);
    uint4 hv = prH[lane];
    uint4 lv = prL[lane];
    float s0 = 0.f, s1 = 0.f, s2 = 0.f;
    const uint32_t hw[4] = {hv.x, hv.y, hv.z, hv.w};
    const uint32_t lw[4] = {lv.x, lv.y, lv.z, lv.w};
    #pragma unroll
    for (int q = 0; q < 4; q++) {
        float2 hf = __bfloat1622float2(*(const __nv_bfloat162*)&hw[q]);
        float2 lf = __bfloat1622float2(*(const __nv_bfloat162*)&lw[q]);
        int i = lane * 8 + q * 2;
        float p0 = hf.x + lf.x, p1 = hf.y + lf.y;
        s0 = fmaf(p0, w0[i], fmaf(p1, w0[i+1], s0));
        s1 = fmaf(p0, w1[i], fmaf(p1, w1[i+1], s1));
        s2 = fmaf(p0, w2[i], fmaf(p1, w2[i+1], s2));
    }
    #pragma unroll
    for (int o = 16; o; o >>= 1) {
        s0 += __shfl_down_sync(0xffffffffu, s0, o);
        s1 += __shfl_down_sync(0xffffffffu, s1, o);
        s2 += __shfl_down_sync(0xffffffffu, s2, o);
    }
    if (lane == 0) {
        g_koff[row] = s0 + g_consts[1];
        g_pu[row] = s1;
        g_pv[row] = s2;
    }
}

// ---------------- fused attention + gather via mma.sync --------------------
// smem (bytes):
//   AH [96][256]bf16 @0, AL @49152, BH @98304, BL @147456  (512B rows, W-swizzle)
//   Ss float[88][89] @196608 (31328 B)
//   koffS @227936 (88f), puS @228288, pvS @228640, dnS @228992 (8f)
#define AT_AH   0
#define AT_AL   49152
#define AT_BH   98304
#define AT_BL   147456
#define AT_SS   196608
#define AT_KOFF 227936
#define AT_PU   228288
#define AT_PV   228640
#define AT_DN   228992
#define AT_TOTAL 229024

__global__ __launch_bounds__(256, 1)
void attn_mma(float* __restrict__ out)
{
    extern __shared__ char smem[];
    const uint32_t sb = smem_u32(smem);
    const int b = blockIdx.x;
    const int tid = threadIdx.x;
    const int wid = tid >> 5;
    const int lane = tid & 31;
    const int wm = wid >> 2;        // 0..1 : 48 rows each
    const int wn = wid & 3;         // 0..3 : 24 cols each

    float* Ss    = (float*)(smem + AT_SS);
    float* koffS = (float*)(smem + AT_KOFF);
    float* puS   = (float*)(smem + AT_PU);
    float* pvS   = (float*)(smem + AT_PV);
    float* dnS   = (float*)(smem + AT_DN);

    // zero pad rows: A rows 88..95 (4096 B each buf), B rows 81..95 (7680 B each)
    const uint4 zz = {0u, 0u, 0u, 0u};
    for (int i = tid; i < 256; i += 256) {
        *(uint4*)(smem + AT_AH + 88 * 512 + i * 16) = zz;
        *(uint4*)(smem + AT_AL + 88 * 512 + i * 16) = zz;
    }
    for (int i = tid; i < 480; i += 256) {
        *(uint4*)(smem + AT_BH + 81 * 512 + i * 16) = zz;
        *(uint4*)(smem + AT_BL + 81 * 512 + i * 16) = zz;
    }

    const __nv_bfloat16* GH  = g_GH  + (size_t)b * 81 * 256;
    const __nv_bfloat16* GL  = g_GL  + (size_t)b * 81 * 256;
    const __nv_bfloat16* PH  = g_peH + (size_t)b * 81 * 256;
    const __nv_bfloat16* PL  = g_peL + (size_t)b * 81 * 256;

    // A: rows 0..80 = G, 81..87 = Dq2
    for (int p = tid; p < 88 * 32; p += 256) {
        int row = p >> 5, unit = p & 31;
        uint32_t off = (uint32_t)row * 512u + (uint32_t)((unit & 24) | ((unit ^ row) & 7)) * 16u;
        const __nv_bfloat16* sh = (row < 81) ? GH + (size_t)row * 256 + unit * 8
                                             : g_Dq2H + (size_t)(row - 81) * 256 + unit * 8;
        const __nv_bfloat16* sl = (row < 81) ? GL + (size_t)row * 256 + unit * 8
                                             : g_Dq2L + (size_t)(row - 81) * 256 + unit * 8;
        CP_ASYNC16(sb + AT_AH + off, sh);
        CP_ASYNC16(sb + AT_AL + off, sl);
    }
    // B: pe rows 0..80
    for (int p = tid; p < 81 * 32; p += 256) {
        int row = p >> 5, unit = p & 31;
        uint32_t off = (uint32_t)row * 512u + (uint32_t)((unit & 24) | ((unit ^ row) & 7)) * 16u;
        CP_ASYNC16(sb + AT_BH + off, PH + (size_t)row * 256 + unit * 8);
        CP_ASYNC16(sb + AT_BL + off, PL + (size_t)row * 256 + unit * 8);
    }
    CP_COMMIT();

    if (tid < 88) {
        koffS[tid] = (tid < 81) ? g_koff[(size_t)b * 81 + tid] : 0.f;
        puS[tid]   = (tid < 81) ? g_pu[(size_t)b * 81 + tid] : 0.f;
        pvS[tid]   = (tid < 81) ? g_pv[(size_t)b * 81 + tid] : 0.f;
    }
    if (tid < 8) dnS[tid] = (tid < NDROP_) ? g_dn[tid] : 0.f;

    CP_WAIT0();
    __syncthreads();

    // warp tile 48(m) x 24(n): 3 m16 x 3 n8 frags
    float acc[3][3][4];
    #pragma unroll
    for (int mi = 0; mi < 3; mi++)
        #pragma unroll
        for (int nj = 0; nj < 3; nj++)
            #pragma unroll
            for (int r = 0; r < 4; r++) acc[mi][nj][r] = 0.f;

    #pragma unroll 4
    for (int k16 = 0; k16 < 16; k16++) {
        uint32_t ah[3][4], al[3][4];
        #pragma unroll
        for (int mi = 0; mi < 3; mi++) {
            int row = wm * 48 + mi * 16 + (lane & 15);
            int u = 2 * k16 + (lane >> 4);
            uint32_t off = (uint32_t)row * 512u + (uint32_t)((u & 24) | ((u ^ row) & 7)) * 16u;
            LDSM4(ah[mi], sb + AT_AH + off);
            LDSM4(al[mi], sb + AT_AL + off);
        }
        uint32_t bh[3][2], bl[3][2];
        {
            int rowb = wn * 24 + (lane & 7) + ((lane >> 1) & 8);
            int u = 2 * k16 + ((lane >> 3) & 1);
            uint32_t off = (uint32_t)rowb * 512u + (uint32_t)((u & 24) | ((u ^ rowb) & 7)) * 16u;
            uint32_t t[4];
            LDSM4(t, sb + AT_BH + off);
            bh[0][0] = t[0]; bh[0][1] = t[1]; bh[1][0] = t[2]; bh[1][1] = t[3];
            LDSM4(t, sb + AT_BL + off);
            bl[0][0] = t[0]; bl[0][1] = t[1]; bl[1][0] = t[2]; bl[1][1] = t[3];
            int rowb2 = rowb + 16;
            uint32_t off2 = (uint32_t)rowb2 * 512u + (uint32_t)((u & 24) | ((u ^ rowb2) & 7)) * 16u;
            LDSM4(t, sb + AT_BH + off2);
            bh[2][0] = t[0]; bh[2][1] = t[1];
            LDSM4(t, sb + AT_BL + off2);
            bl[2][0] = t[0]; bl[2][1] = t[1];
        }
        #pragma unroll
        for (int mi = 0; mi < 3; mi++)
            #pragma unroll
            for (int nj = 0; nj < 3; nj++) {
                MMA_BF16(acc[mi][nj], ah[mi], bh[nj]);
                MMA_BF16(acc[mi][nj], ah[mi], bl[nj]);
                MMA_BF16(acc[mi][nj], al[mi], bh[nj]);
            }
    }

    // epilogue: corrections -> Ss
    const float cC = g_consts[0];
    #pragma unroll
    for (int mi = 0; mi < 3; mi++) {
        #pragma unroll
        for (int half = 0; half < 2; half++) {
            int r = wm * 48 + mi * 16 + half * 8 + (lane >> 2);
            if (r < 88) {
                #pragma unroll
                for (int nj = 0; nj < 3; nj++) {
                    int c = wn * 24 + nj * 8 + 2 * (lane & 3);
                    if (c < 81) {
                        float corr0 = (r < 81) ? (puS[r] + pvS[c] + cC) : dnS[r - 81];
                        float corr1 = (r < 81) ? (puS[r] + pvS[c + 1] + cC) : dnS[r - 81];
                        Ss[r * 89 + c]     = acc[mi][nj][half * 2 + 0] + corr0;
                        Ss[r * 89 + c + 1] = acc[mi][nj][half * 2 + 1] + corr1;
                    }
                }
            }
        }
    }
    __syncthreads();

    // gather
    for (int p = tid; p < P_; p += 256) {
        int code = g_src2[p];
        int col = code & 127;
        int row = (code >> 7) & 127;
        float v = Ss[row * 89 + col];
        if (code & (1 << 14)) v += koffS[col];
        out[(size_t)b * P_ + p] = v;
    }
}

// ---------------- launch ----------------
extern "C" void kernel_launch(void* const* d_in, const int* in_sizes, int n_in,
                              void* d_out, int out_size)
{
    const float* x    = (const float*)d_in[0];
    const float* We   = (const float*)d_in[1];
    const float* be   = (const float*)d_in[2];
    const float* Wq   = (const float*)d_in[3];
    const float* bq   = (const float*)d_in[4];
    const float* Wk   = (const float*)d_in[5];
    const float* bk   = (const float*)d_in[6];
    const float* Wp   = (const float*)d_in[7];
    const float* bp   = (const float*)d_in[8];
    const float* Dq   = (const float*)d_in[9];
    const void*  vraw = d_in[10];
    const void*  vpol = d_in[11];
    float* out = (float*)d_out;

    cudaFuncSetAttribute(tc_gemm1, cudaFuncAttributeMaxDynamicSharedMemorySize, GS_TOTAL);
    cudaFuncSetAttribute(tc_gemm2, cudaFuncAttributeMaxDynamicSharedMemorySize, GS_TOTAL);
    cudaFuncSetAttribute(attn_mma, cudaFuncAttributeMaxDynamicSharedMemorySize, AT_TOTAL);

    prep_weights<<<258, 256>>>(Wq, Wk, Wp, bq, bk, bp, Dq);
    prep_split<<<257, 256>>>(We);
    prep_src<<<(P_ + 255) / 256, 256>>>(vraw, vpol);
    tc_gemm1<<<dim3(MROWS / 128, 2), 256, GS_TOTAL>>>(x, be);   // pe = mish(x@We+be), split
    tc_gemm2<<<dim3(MROWS / 128, 2), 256, GS_TOTAL>>>();        // G = pe@A, split
    koff_kernel<<<MROWS / 8, 256>>>();
    attn_mma<<<B_, 256, AT_TOTAL>>>(out);
}

// round 10
// speedup vs baseline: 1.0016x; 1.0016x over previous
#include <cuda_runtime.h>
#include <cuda_bf16.h>
#include <math.h>
#include <stdint.h>

// Problem constants
#define B_      4096
#define SQ_     81
#define D_      256
#define P_      3849
#define NDROP_  7
#define MROWS   (B_ * SQ_)          // 331776
#define SCALE_  0.0625f             // 1/sqrt(256)

// ---------------- device scratch (static, no allocs) ----------------
__device__ __nv_bfloat16 g_peH[84934656], g_peL[84934656];   // pe split (MROWS*256)
__device__ __nv_bfloat16 g_GH [84934656], g_GL [84934656];   // G split
__device__ float g_A [D_ * D_];     // s * Wq @ Wk^T
__device__ float g_Dq2[NDROP_ * D_];// s * Dq @ Wk^T
__device__ __nv_bfloat16 g_Dq2H[NDROP_ * D_], g_Dq2L[NDROP_ * D_];
__device__ float g_wkp[D_];         // Wk @ Wp
__device__ float g_u[D_];           // s * Wq @ bk
__device__ float g_v[D_];           // s * Wk @ bq
__device__ float g_koff[MROWS];
__device__ float g_pu[MROWS];
__device__ float g_pv[MROWS];
__device__ float g_dn[NDROP_];      // s * Dq @ bk
__device__ float g_consts[2];       // [0] = s*(bq.bk), [1] = bk.Wp + bp
__device__ int   g_src2[P_];        // packed col | row<<7 | promo<<14

// bf16 split weights (transposed to [n][k]):
__device__ __nv_bfloat16 g_W1h[65536], g_W1l[65536];   // We^T  hi/lo
__device__ __nv_bfloat16 g_W2h[65536], g_W2l[65536];   // A^T   hi/lo

// ================= portable PTX helpers (sm_80+ ISA only) =================
__device__ __forceinline__ uint32_t smem_u32(const void* p) {
    uint32_t a;
    asm("{ .reg .u64 t; cvta.to.shared.u64 t, %1; cvt.u32.u64 %0, t; }" : "=r"(a) : "l"(p));
    return a;
}

#define LDSM4(r, addr) \
    asm volatile("ldmatrix.sync.aligned.m8n8.x4.shared.b16 {%0,%1,%2,%3}, [%4];" \
        : "=r"((r)[0]), "=r"((r)[1]), "=r"((r)[2]), "=r"((r)[3]) : "r"(addr))

#define MMA_BF16(c, a, b) \
    asm volatile("mma.sync.aligned.m16n8k16.row.col.f32.bf16.bf16.f32 " \
        "{%0,%1,%2,%3}, {%4,%5,%6,%7}, {%8,%9}, {%0,%1,%2,%3};" \
        : "+f"((c)[0]), "+f"((c)[1]), "+f"((c)[2]), "+f"((c)[3]) \
        : "r"((a)[0]), "r"((a)[1]), "r"((a)[2]), "r"((a)[3]), \
          "r"((b)[0]), "r"((b)[1]))

#define CP_ASYNC16(saddr, gptr) \
    asm volatile("cp.async.cg.shared.global [%0], [%1], 16;" :: "r"(saddr), "l"(gptr))
#define CP_COMMIT()  asm volatile("cp.async.commit_group;" ::: "memory")
#define CP_WAIT0()   asm volatile("cp.async.wait_group 0;" ::: "memory")
#define CP_WAIT1()   asm volatile("cp.async.wait_group 1;" ::: "memory")

__device__ __forceinline__ float mishf(float v)
{
    float sp = fmaxf(v, 0.f) + log1pf(__expf(-fabsf(v)));
    return v * tanhf(sp);
}

__device__ __forceinline__ void split2(float v0, float v1,
                                       __nv_bfloat162& h, __nv_bfloat162& l)
{
    h = __floats2bfloat162_rn(v0, v1);
    float2 hf = __bfloat1622float2(h);
    l = __floats2bfloat162_rn(v0 - hf.x, v1 - hf.y);
}

// ---------------- prep: small weight products ----------------
__global__ __launch_bounds__(256)
void prep_weights(const float* __restrict__ Wq, const float* __restrict__ Wk,
                  const float* __restrict__ Wp, const float* __restrict__ bq,
                  const float* __restrict__ bk, const float* __restrict__ bp,
                  const float* __restrict__ Dq)
{
    int blk = blockIdx.x;
    int t = threadIdx.x;
    if (blk < 256) {
        __shared__ float wq[256];
        wq[t] = Wq[blk * 256 + t];
        __syncthreads();
        const float* wkrow = Wk + (size_t)t * 256;
        float acc = 0.f;
        #pragma unroll 8
        for (int i = 0; i < 256; i++) acc = fmaf(wq[i], wkrow[i], acc);
        g_A[blk * 256 + t] = SCALE_ * acc;
    } else if (blk == 256) {
        __shared__ float dq[NDROP_ * 256];
        for (int idx = t; idx < NDROP_ * 256; idx += 256) dq[idx] = Dq[idx];
        __syncthreads();
        const float* wkrow = Wk + (size_t)t * 256;
        float a[NDROP_];
        #pragma unroll
        for (int n = 0; n < NDROP_; n++) a[n] = 0.f;
        for (int i = 0; i < 256; i++) {
            float w = wkrow[i];
            #pragma unroll
            for (int n = 0; n < NDROP_; n++) a[n] = fmaf(dq[n * 256 + i], w, a[n]);
        }
        #pragma unroll
        for (int n = 0; n < NDROP_; n++) g_Dq2[n * 256 + t] = SCALE_ * a[n];
    } else {
        __shared__ float wp[256], bks[256], bqs[256];
        wp[t] = Wp[t]; bks[t] = bk[t]; bqs[t] = bq[t];
        __syncthreads();
        const float* wkrow = Wk + (size_t)t * 256;
        const float* wqrow = Wq + (size_t)t * 256;
        float a0 = 0.f, a1 = 0.f, a2 = 0.f;
        for (int i = 0; i < 256; i++) {
            a0 = fmaf(wkrow[i], wp[i],  a0);
            a1 = fmaf(wqrow[i], bks[i], a1);
            a2 = fmaf(wkrow[i], bqs[i], a2);
        }
        g_wkp[t] = a0;
        g_u[t]   = SCALE_ * a1;
        g_v[t]   = SCALE_ * a2;
        if (t < NDROP_) {
            float s = 0.f;
            for (int i = 0; i < 256; i++) s = fmaf(Dq[t * 256 + i], bks[i], s);
            g_dn[t] = SCALE_ * s;
        }
        if (t == 0) {
            float c = 0.f, kb = 0.f;
            for (int i = 0; i < 256; i++) { c = fmaf(bqs[i], bks[i], c); kb = fmaf(bks[i], wp[i], kb); }
            g_consts[0] = SCALE_ * c;
            g_consts[1] = kb + bp[0];
        }
    }
}

// ---------------- prep: bf16 hi/lo splits -------------
__global__ __launch_bounds__(256)
void prep_split(const float* __restrict__ We)
{
    int n = blockIdx.x, k = threadIdx.x;
    if (n < 256) {
        float v1 = We[(size_t)k * 256 + n];              // We^T[n][k]
        __nv_bfloat16 h1 = __float2bfloat16(v1);
        g_W1h[n * 256 + k] = h1;
        g_W1l[n * 256 + k] = __float2bfloat16(v1 - __bfloat162float(h1));
        float v2 = g_A[(size_t)k * 256 + n];             // A^T[n][k]
        __nv_bfloat16 h2 = __float2bfloat16(v2);
        g_W2h[n * 256 + k] = h2;
        g_W2l[n * 256 + k] = __float2bfloat16(v2 - __bfloat162float(h2));
    } else {
        #pragma unroll
        for (int d = 0; d < NDROP_; d++) {
            float v = g_Dq2[d * 256 + k];
            __nv_bfloat16 h = __float2bfloat16(v);
            g_Dq2H[d * 256 + k] = h;
            g_Dq2L[d * 256 + k] = __float2bfloat16(v - __bfloat162float(h));
        }
    }
}

// ---------------- prep: inverse scatter map ----------------
__global__ void prep_src(const void* __restrict__ vraw, const void* __restrict__ vpol)
{
    const int* r32 = (const int*)vraw;
    bool is64 = (r32[1] == 0 && r32[3] == 0 && r32[5] == 0);
    int j = blockIdx.x * blockDim.x + threadIdx.x;
    if (j >= P_) return;
    long long r, pol;
    if (is64) {
        r   = ((const long long*)vraw)[j];
        pol = ((const long long*)vpol)[j];
    } else {
        r   = ((const int*)vraw)[j];
        pol = ((const int*)vpol)[j];
    }
    int ri = (int)r;
    int row, col, promo = 0;
    if (ri < 6561)       { row = ri / 81;               col = ri % 81; }
    else if (ri < 13122) { int u2 = ri - 6561;  row = u2 / 81;      col = u2 % 81; promo = 1; }
    else                 { int u2 = ri - 13122; row = 81 + u2 / 81; col = u2 % 81; }
    g_src2[(int)pol] = col | (row << 7) | (promo << 14);
}

// ================== GEMM1: pe = mish(x @ We + be), split-bf16 mma ==========
// smem: WH 0..64K, WL 64K..128K (resident), X 128K.. (2 stages x (hi16K+lo16K))
#define GS_WH   0
#define GS_WL   65536
#define GS_X    131072
#define GS_TOTAL 196608

__global__ __launch_bounds__(256, 1)
void tc_gemm1(const float* __restrict__ xin, const float* __restrict__ be)
{
    extern __shared__ char smem[];
    __shared__ float biasS[128];
    const uint32_t sb = smem_u32(smem);
    const int tid  = threadIdx.x;
    const int wid  = tid >> 5;
    const int lane = tid & 31;
    const int wm   = wid & 3;
    const int wn   = wid >> 2;
    const int m0 = blockIdx.x * 128;
    const int n0 = blockIdx.y * 128;

    const float* __restrict__ Xg = xin;
    const __nv_bfloat16* __restrict__ Wh = g_W1h + (size_t)n0 * 256;
    const __nv_bfloat16* __restrict__ Wl = g_W1l + (size_t)n0 * 256;

    if (tid < 128) biasS[tid] = be[n0 + tid];

    // resident W tiles (hi+lo), swizzled 512B rows
    #pragma unroll
    for (int i = 0; i < 32; i++) {
        int p = tid + i * 256;
        int half = p >> 12;
        int q = p & 4095;
        int row = q >> 5;
        int unit = q & 31;
        int phys = (unit & 24) | ((unit ^ row) & 7);
        uint32_t saddr = sb + (uint32_t)half * 65536u + (uint32_t)row * 512u + (uint32_t)phys * 16u;
        const __nv_bfloat16* gp = (half ? Wl : Wh) + (size_t)row * 256 + unit * 8;
        CP_ASYNC16(saddr, gp);
    }
    CP_COMMIT();

    const float* Xblk = Xg + (size_t)m0 * 256;
    float4 v[8];
    #pragma unroll
    for (int i = 0; i < 8; i++) {
        int p = tid + i * 256;
        int row = p >> 4, k4 = p & 15;
        v[i] = *(const float4*)(Xblk + (size_t)row * 256 + k4 * 4);
    }
    #pragma unroll
    for (int i = 0; i < 8; i++) {
        int p = tid + i * 256;
        int row = p >> 4, k4 = p & 15;
        int unit = k4 >> 1, sub = k4 & 1;
        uint32_t off = (uint32_t)row * 128u + (uint32_t)(((unit ^ row) & 7)) * 16u + (uint32_t)sub * 8u;
        __nv_bfloat162 h0, h1, l0, l1;
        split2(v[i].x, v[i].y, h0, l0);
        split2(v[i].z, v[i].w, h1, l1);
        uint2 hv, lv;
        hv.x = *(uint32_t*)&h0; hv.y = *(uint32_t*)&h1;
        lv.x = *(uint32_t*)&l0; lv.y = *(uint32_t*)&l1;
        *(uint2*)(smem + GS_X + off) = hv;
        *(uint2*)(smem + GS_X + 16384 + off) = lv;
    }
    CP_WAIT0();
    __syncthreads();

    float acc[2][8][4];
    #pragma unroll
    for (int mi = 0; mi < 2; mi++)
        #pragma unroll
        for (int nj = 0; nj < 8; nj++)
            #pragma unroll
            for (int r = 0; r < 4; r++) acc[mi][nj][r] = 0.f;

    for (int kc = 0; kc < 4; kc++) {
        const int buf = kc & 1;
        const uint32_t xh = sb + GS_X + (uint32_t)buf * 32768u;
        const uint32_t xl = xh + 16384u;

        if (kc < 3) {
            #pragma unroll
            for (int i = 0; i < 8; i++) {
                int p = tid + i * 256;
                int row = p >> 4, k4 = p & 15;
                v[i] = *(const float4*)(Xblk + (size_t)row * 256 + (kc + 1) * 64 + k4 * 4);
            }
        }

        #pragma unroll
        for (int k16 = 0; k16 < 4; k16++) {
            uint32_t ah[2][4], al[2][4];
            #pragma unroll
            for (int mi = 0; mi < 2; mi++) {
                int row = wm * 32 + mi * 16 + (lane & 15);
                int u = 2 * k16 + (lane >> 4);
                uint32_t off = (uint32_t)row * 128u + (uint32_t)((u ^ row) & 7) * 16u;
                LDSM4(ah[mi], xh + off);
                LDSM4(al[mi], xl + off);
            }
            uint32_t bh[8][2], bl[8][2];
            const int kk = kc * 4 + k16;
            #pragma unroll
            for (int j = 0; j < 4; j++) {
                int row = wn * 64 + j * 16 + (lane & 7) + ((lane >> 1) & 8);
                int u = 2 * kk + ((lane >> 3) & 1);
                uint32_t off = (uint32_t)row * 512u + (uint32_t)((u & 24) | ((u ^ row) & 7)) * 16u;
                uint32_t t[4];
                LDSM4(t, sb + GS_WH + off);
                bh[2*j][0] = t[0]; bh[2*j][1] = t[1]; bh[2*j+1][0] = t[2]; bh[2*j+1][1] = t[3];
                LDSM4(t, sb + GS_WL + off);
                bl[2*j][0] = t[0]; bl[2*j][1] = t[1]; bl[2*j+1][0] = t[2]; bl[2*j+1][1] = t[3];
            }
            #pragma unroll
            for (int mi = 0; mi < 2; mi++)
                #pragma unroll
                for (int nj = 0; nj < 8; nj++) {
                    MMA_BF16(acc[mi][nj], ah[mi], bh[nj]);
                    MMA_BF16(acc[mi][nj], ah[mi], bl[nj]);
                    MMA_BF16(acc[mi][nj], al[mi], bh[nj]);
                }
        }

        if (kc < 3) {
            const uint32_t nbuf = (kc + 1) & 1;
            __syncthreads();
            #pragma unroll
            for (int i = 0; i < 8; i++) {
                int p = tid + i * 256;
                int row = p >> 4, k4 = p & 15;
                int unit = k4 >> 1, sub = k4 & 1;
                uint32_t off = (uint32_t)nbuf * 32768u + (uint32_t)row * 128u
                             + (uint32_t)(((unit ^ row) & 7)) * 16u + (uint32_t)sub * 8u;
                __nv_bfloat162 h0, h1, l0, l1;
                split2(v[i].x, v[i].y, h0, l0);
                split2(v[i].z, v[i].w, h1, l1);
                uint2 hv, lv;
                hv.x = *(uint32_t*)&h0; hv.y = *(uint32_t*)&h1;
                lv.x = *(uint32_t*)&l0; lv.y = *(uint32_t*)&l1;
                *(uint2*)(smem + GS_X + off) = hv;
                *(uint2*)(smem + GS_X + 16384 + off) = lv;
            }
            __syncthreads();
        }
    }

    // epilogue: mish + split-bf16 write of pe
    const int mrow0 = m0 + wm * 32;
    const int ncol0 = wn * 64;
    #pragma unroll
    for (int mi = 0; mi < 2; mi++) {
        #pragma unroll
        for (int half = 0; half < 2; half++) {
            int m = mrow0 + mi * 16 + half * 8 + (lane >> 2);
            #pragma unroll
            for (int nj = 0; nj < 8; nj++) {
                int cl = ncol0 + nj * 8 + 2 * (lane & 3);
                float v0 = mishf(acc[mi][nj][half * 2 + 0] + biasS[cl]);
                float v1 = mishf(acc[mi][nj][half * 2 + 1] + biasS[cl + 1]);
                __nv_bfloat162 h, l;
                split2(v0, v1, h, l);
                *(__nv_bfloat162*)(g_peH + (size_t)m * 256 + n0 + cl) = h;
                *(__nv_bfloat162*)(g_peL + (size_t)m * 256 + n0 + cl) = l;
            }
        }
    }
}

// ================== GEMM2: G = pe @ A^T, pure cp.async/bf16 loop ===========
__global__ __launch_bounds__(256, 1)
void tc_gemm2()
{
    extern __shared__ char smem[];
    const uint32_t sb = smem_u32(smem);
    const int tid  = threadIdx.x;
    const int wid  = tid >> 5;
    const int lane = tid & 31;
    const int wm   = wid & 3;
    const int wn   = wid >> 2;
    const int m0 = blockIdx.x * 128;
    const int n0 = blockIdx.y * 128;

    const __nv_bfloat16* __restrict__ Wh = g_W2h + (size_t)n0 * 256;
    const __nv_bfloat16* __restrict__ Wl = g_W2l + (size_t)n0 * 256;

    // group 0: resident W
    #pragma unroll
    for (int i = 0; i < 32; i++) {
        int p = tid + i * 256;
        int half = p >> 12;
        int q = p & 4095;
        int row = q >> 5;
        int unit = q & 31;
        int phys = (unit & 24) | ((unit ^ row) & 7);
        uint32_t saddr = sb + (uint32_t)half * 65536u + (uint32_t)row * 512u + (uint32_t)phys * 16u;
        const __nv_bfloat16* gp = (half ? Wl : Wh) + (size_t)row * 256 + unit * 8;
        CP_ASYNC16(saddr, gp);
    }
    CP_COMMIT();

    // X stages: [128 rows][64 k] bf16, 128B rows, hi+lo
    auto issue_stage = [&](int kc) {
        const uint32_t st = GS_X + (uint32_t)(kc & 1) * 32768u;
        #pragma unroll
        for (int half = 0; half < 2; half++) {
            const __nv_bfloat16* src = (half ? g_peL : g_peH);
            #pragma unroll
            for (int i = 0; i < 4; i++) {
                int p = tid + i * 256;          // 0..1023
                int row = p >> 3, unit = p & 7;
                uint32_t off = st + (uint32_t)half * 16384u + (uint32_t)row * 128u
                             + (uint32_t)((unit ^ row) & 7) * 16u;
                CP_ASYNC16(sb + off, src + (size_t)(m0 + row) * 256 + kc * 64 + unit * 8);
            }
        }
        CP_COMMIT();
    };
    issue_stage(0);
    issue_stage(1);

    float acc[2][8][4];
    #pragma unroll
    for (int mi = 0; mi < 2; mi++)
        #pragma unroll
        for (int nj = 0; nj < 8; nj++)
            #pragma unroll
            for (int r = 0; r < 4; r++) acc[mi][nj][r] = 0.f;

    for (int kc = 0; kc < 4; kc++) {
        if (kc < 3) { CP_WAIT1(); } else { CP_WAIT0(); }
        __syncthreads();
        const uint32_t xh = sb + GS_X + (uint32_t)(kc & 1) * 32768u;
        const uint32_t xl = xh + 16384u;

        #pragma unroll
        for (int k16 = 0; k16 < 4; k16++) {
            uint32_t ah[2][4], al[2][4];
            #pragma unroll
            for (int mi = 0; mi < 2; mi++) {
                int row = wm * 32 + mi * 16 + (lane & 15);
                int u = 2 * k16 + (lane >> 4);
                uint32_t off = (uint32_t)row * 128u + (uint32_t)((u ^ row) & 7) * 16u;
                LDSM4(ah[mi], xh + off);
                LDSM4(al[mi], xl + off);
            }
            uint32_t bh[8][2], bl[8][2];
            const int kk = kc * 4 + k16;
            #pragma unroll
            for (int j = 0; j < 4; j++) {
                int row = wn * 64 + j * 16 + (lane & 7) + ((lane >> 1) & 8);
                int u = 2 * kk + ((lane >> 3) & 1);
                uint32_t off = (uint32_t)row * 512u + (uint32_t)((u & 24) | ((u ^ row) & 7)) * 16u;
                uint32_t t[4];
                LDSM4(t, sb + GS_WH + off);
                bh[2*j][0] = t[0]; bh[2*j][1] = t[1]; bh[2*j+1][0] = t[2]; bh[2*j+1][1] = t[3];
                LDSM4(t, sb + GS_WL + off);
                bl[2*j][0] = t[0]; bl[2*j][1] = t[1]; bl[2*j+1][0] = t[2]; bl[2*j+1][1] = t[3];
            }
            #pragma unroll
            for (int mi = 0; mi < 2; mi++)
                #pragma unroll
                for (int nj = 0; nj < 8; nj++) {
                    MMA_BF16(acc[mi][nj], ah[mi], bh[nj]);
                    MMA_BF16(acc[mi][nj], ah[mi], bl[nj]);
                    MMA_BF16(acc[mi][nj], al[mi], bh[nj]);
                }
        }
        __syncthreads();
        if (kc < 2) issue_stage(kc + 2);
    }

    // epilogue: split-bf16 write of G
    const int mrow0 = m0 + wm * 32;
    const int ncol0 = wn * 64;
    #pragma unroll
    for (int mi = 0; mi < 2; mi++) {
        #pragma unroll
        for (int half = 0; half < 2; half++) {
            int m = mrow0 + mi * 16 + half * 8 + (lane >> 2);
            #pragma unroll
            for (int nj = 0; nj < 8; nj++) {
                int cl = ncol0 + nj * 8 + 2 * (lane & 3);
                __nv_bfloat162 h, l;
                split2(acc[mi][nj][half * 2 + 0], acc[mi][nj][half * 2 + 1], h, l);
                *(__nv_bfloat162*)(g_GH + (size_t)m * 256 + n0 + cl) = h;
                *(__nv_bfloat162*)(g_GL + (size_t)m * 256 + n0 + cl) = l;
            }
        }
    }
}

// ---------------- per-row dots: koff / pu / pv (split-pe input) ------------
__global__ __launch_bounds__(256)
void koff_kernel()
{
    __shared__ float w0[256], w1[256], w2[256];
    int t = threadIdx.x;
    w0[t] = g_wkp[t]; w1[t] = g_u[t]; w2[t] = g_v[t];
    __syncthreads();
    int warp = t >> 5, lane = t & 31;
    int row = blockIdx.x * 8 + warp;
    const uint4* prH = (const uint4*)(g_peH + (size_t)row * 256);
    const uint4* prL = (const uint4*)(g_peL + (size_t)row * 256);
    uint4 hv = prH[lane];
    uint4 lv = prL[lane];
    float s0 = 0.f, s1 = 0.f, s2 = 0.f;
    const uint32_t hw[4] = {hv.x, hv.y, hv.z, hv.w};
    const uint32_t lw[4] = {lv.x, lv.y, lv.z, lv.w};
    #pragma unroll
    for (int q = 0; q < 4; q++) {
        float2 hf = __bfloat1622float2(*(const __nv_bfloat162*)&hw[q]);
        float2 lf = __bfloat1622float2(*(const __nv_bfloat162*)&lw[q]);
        int i = lane * 8 + q * 2;
        float p0 = hf.x + lf.x, p1 = hf.y + lf.y;
        s0 = fmaf(p0, w0[i], fmaf(p1, w0[i+1], s0));
        s1 = fmaf(p0, w1[i], fmaf(p1, w1[i+1], s1));
        s2 = fmaf(p0, w2[i], fmaf(p1, w2[i+1], s2));
    }
    #pragma unroll
    for (int o = 16; o; o >>= 1) {
        s0 += __shfl_down_sync(0xffffffffu, s0, o);
        s1 += __shfl_down_sync(0xffffffffu, s1, o);
        s2 += __shfl_down_sync(0xffffffffu, s2, o);
    }
    if (lane == 0) {
        g_koff[row] = s0 + g_consts[1];
        g_pu[row] = s1;
        g_pv[row] = s2;
    }
}

// ---------------- fused attention + gather via mma.sync --------------------
// smem (bytes):
//   AH [96][256]bf16 @0, AL @49152, BH @98304, BL @147456  (512B rows, W-swizzle)
//   Ss float[88][89] @196608 (31328 B)
//   koffS @227936 (88f), puS @228288, pvS @228640, dnS @228992 (8f)
#define AT_AH   0
#define AT_AL   49152
#define AT_BH   98304
#define AT_BL   147456
#define AT_SS   196608
#define AT_KOFF 227936
#define AT_PU   228288
#define AT_PV   228640
#define AT_DN   228992
#define AT_TOTAL 229024

__global__ __launch_bounds__(256, 1)
void attn_mma(float* __restrict__ out)
{
    extern __shared__ char smem[];
    const uint32_t sb = smem_u32(smem);
    const int b = blockIdx.x;
    const int tid = threadIdx.x;
    const int wid = tid >> 5;
    const int lane = tid & 31;
    const int wm = wid >> 2;        // 0..1 : 48 rows each
    const int wn = wid & 3;         // 0..3 : 24 cols each

    float* Ss    = (float*)(smem + AT_SS);
    float* koffS = (float*)(smem + AT_KOFF);
    float* puS   = (float*)(smem + AT_PU);
    float* pvS   = (float*)(smem + AT_PV);
    float* dnS   = (float*)(smem + AT_DN);

    // zero pad rows: A rows 88..95 (4096 B each buf), B rows 81..95 (7680 B each)
    const uint4 zz = {0u, 0u, 0u, 0u};
    for (int i = tid; i < 256; i += 256) {
        *(uint4*)(smem + AT_AH + 88 * 512 + i * 16) = zz;
        *(uint4*)(smem + AT_AL + 88 * 512 + i * 16) = zz;
    }
    for (int i = tid; i < 480; i += 256) {
        *(uint4*)(smem + AT_BH + 81 * 512 + i * 16) = zz;
        *(uint4*)(smem + AT_BL + 81 * 512 + i * 16) = zz;
    }

    const __nv_bfloat16* GH  = g_GH  + (size_t)b * 81 * 256;
    const __nv_bfloat16* GL  = g_GL  + (size_t)b * 81 * 256;
    const __nv_bfloat16* PH  = g_peH + (size_t)b * 81 * 256;
    const __nv_bfloat16* PL  = g_peL + (size_t)b * 81 * 256;

    // A: rows 0..80 = G, 81..87 = Dq2
    for (int p = tid; p < 88 * 32; p += 256) {
        int row = p >> 5, unit = p & 31;
        uint32_t off = (uint32_t)row * 512u + (uint32_t)((unit & 24) | ((unit ^ row) & 7)) * 16u;
        const __nv_bfloat16* sh = (row < 81) ? GH + (size_t)row * 256 + unit * 8
                                             : g_Dq2H + (size_t)(row - 81) * 256 + unit * 8;
        const __nv_bfloat16* sl = (row < 81) ? GL + (size_t)row * 256 + unit * 8
                                             : g_Dq2L + (size_t)(row - 81) * 256 + unit * 8;
        CP_ASYNC16(sb + AT_AH + off, sh);
        CP_ASYNC16(sb + AT_AL + off, sl);
    }
    // B: pe rows 0..80
    for (int p = tid; p < 81 * 32; p += 256) {
        int row = p >> 5, unit = p & 31;
        uint32_t off = (uint32_t)row * 512u + (uint32_t)((unit & 24) | ((unit ^ row) & 7)) * 16u;
        CP_ASYNC16(sb + AT_BH + off, PH + (size_t)row * 256 + unit * 8);
        CP_ASYNC16(sb + AT_BL + off, PL + (size_t)row * 256 + unit * 8);
    }
    CP_COMMIT();

    if (tid < 88) {
        koffS[tid] = (tid < 81) ? g_koff[(size_t)b * 81 + tid] : 0.f;
        puS[tid]   = (tid < 81) ? g_pu[(size_t)b * 81 + tid] : 0.f;
        pvS[tid]   = (tid < 81) ? g_pv[(size_t)b * 81 + tid] : 0.f;
    }
    if (tid < 8) dnS[tid] = (tid < NDROP_) ? g_dn[tid] : 0.f;

    CP_WAIT0();
    __syncthreads();

    // warp tile 48(m) x 24(n): 3 m16 x 3 n8 frags
    float acc[3][3][4];
    #pragma unroll
    for (int mi = 0; mi < 3; mi++)
        #pragma unroll
        for (int nj = 0; nj < 3; nj++)
            #pragma unroll
            for (int r = 0; r < 4; r++) acc[mi][nj][r] = 0.f;

    #pragma unroll 4
    for (int k16 = 0; k16 < 16; k16++) {
        uint32_t ah[3][4], al[3][4];
        #pragma unroll
        for (int mi = 0; mi < 3; mi++) {
            int row = wm * 48 + mi * 16 + (lane & 15);
            int u = 2 * k16 + (lane >> 4);
            uint32_t off = (uint32_t)row * 512u + (uint32_t)((u & 24) | ((u ^ row) & 7)) * 16u;
            LDSM4(ah[mi], sb + AT_AH + off);
            LDSM4(al[mi], sb + AT_AL + off);
        }
        uint32_t bh[3][2], bl[3][2];
        {
            int rowb = wn * 24 + (lane & 7) + ((lane >> 1) & 8);
            int u = 2 * k16 + ((lane >> 3) & 1);
            uint32_t off = (uint32_t)rowb * 512u + (uint32_t)((u & 24) | ((u ^ rowb) & 7)) * 16u;
            uint32_t t[4];
            LDSM4(t, sb + AT_BH + off);
            bh[0][0] = t[0]; bh[0][1] = t[1]; bh[1][0] = t[2]; bh[1][1] = t[3];
            LDSM4(t, sb + AT_BL + off);
            bl[0][0] = t[0]; bl[0][1] = t[1]; bl[1][0] = t[2]; bl[1][1] = t[3];
            int rowb2 = rowb + 16;
            uint32_t off2 = (uint32_t)rowb2 * 512u + (uint32_t)((u & 24) | ((u ^ rowb2) & 7)) * 16u;
            LDSM4(t, sb + AT_BH + off2);
            bh[2][0] = t[0]; bh[2][1] = t[1];
            LDSM4(t, sb + AT_BL + off2);
            bl[2][0] = t[0]; bl[2][1] = t[1];
        }
        #pragma unroll
        for (int mi = 0; mi < 3; mi++)
            #pragma unroll
            for (int nj = 0; nj < 3; nj++) {
                MMA_BF16(acc[mi][nj], ah[mi], bh[nj]);
                MMA_BF16(acc[mi][nj], ah[mi], bl[nj]);
                MMA_BF16(acc[mi][nj], al[mi], bh[nj]);
            }
    }

    // epilogue: corrections -> Ss
    const float cC = g_consts[0];
    #pragma unroll
    for (int mi = 0; mi < 3; mi++) {
        #pragma unroll
        for (int half = 0; half < 2; half++) {
            int r = wm * 48 + mi * 16 + half * 8 + (lane >> 2);
            if (r < 88) {
                #pragma unroll
                for (int nj = 0; nj < 3; nj++) {
                    int c = wn * 24 + nj * 8 + 2 * (lane & 3);
                    if (c < 81) {
                        float corr0 = (r < 81) ? (puS[r] + pvS[c] + cC) : dnS[r - 81];
                        float corr1 = (r < 81) ? (puS[r] + pvS[c + 1] + cC) : dnS[r - 81];
                        Ss[r * 89 + c]     = acc[mi][nj][half * 2 + 0] + corr0;
                        Ss[r * 89 + c + 1] = acc[mi][nj][half * 2 + 1] + corr1;
                    }
                }
            }
        }
    }
    __syncthreads();

    // gather
    for (int p = tid; p < P_; p += 256) {
        int code = g_src2[p];
        int col = code & 127;
        int row = (code >> 7) & 127;
        float v = Ss[row * 89 + col];
        if (code & (1 << 14)) v += koffS[col];
        out[(size_t)b * P_ + p] = v;
    }
}

// ---------------- launch ----------------
extern "C" void kernel_launch(void* const* d_in, const int* in_sizes, int n_in,
                              void* d_out, int out_size)
{
    const float* x    = (const float*)d_in[0];
    const float* We   = (const float*)d_in[1];
    const float* be   = (const float*)d_in[2];
    const float* Wq   = (const float*)d_in[3];
    const float* bq   = (const float*)d_in[4];
    const float* Wk   = (const float*)d_in[5];
    const float* bk   = (const float*)d_in[6];
    const float* Wp   = (const float*)d_in[7];
    const float* bp   = (const float*)d_in[8];
    const float* Dq   = (const float*)d_in[9];
    const void*  vraw = d_in[10];
    const void*  vpol = d_in[11];
    float* out = (float*)d_out;

    cudaFuncSetAttribute(tc_gemm1, cudaFuncAttributeMaxDynamicSharedMemorySize, GS_TOTAL);
    cudaFuncSetAttribute(tc_gemm2, cudaFuncAttributeMaxDynamicSharedMemorySize, GS_TOTAL);
    cudaFuncSetAttribute(attn_mma, cudaFuncAttributeMaxDynamicSharedMemorySize, AT_TOTAL);

    prep_weights<<<258, 256>>>(Wq, Wk, Wp, bq, bk, bp, Dq);
    prep_split<<<257, 256>>>(We);
    prep_src<<<(P_ + 255) / 256, 256>>>(vraw, vpol);
    tc_gemm1<<<dim3(MROWS / 128, 2), 256, GS_TOTAL>>>(x, be);   // pe = mish(x@We+be), split
    tc_gemm2<<<dim3(MROWS / 128, 2), 256, GS_TOTAL>>>();        // G = pe@A, split
    koff_kernel<<<MROWS / 8, 256>>>();
    attn_mma<<<B_, 256, AT_TOTAL>>>(out);
}